// round 11
// baseline (speedup 1.0000x reference)
#include <cuda_runtime.h>
#include <cuda_fp16.h>
#include <stdint.h>

#define Bq 256
#define Hq 128
#define Nq 2048
#define BN 128            // CTA n-tile (8 warps x 16 cols)
#define BK 32
#define BPS 40            // B private row stride in half2 (conflict-free frags)
// dynamic smem offsets (bytes)
#define OFF_A    0                          // 128 x 128 half2 swizzled = 65536
#define OFF_B    65536                      // 8 warps x 2 bufs x 16 x BPS x 4 = 40960
#define OFF_VS   (OFF_B + 40960)            // 106496: 128 floats
#define OFF_CS   (OFF_VS + 512)             // 107008: 128 floats
#define OFF_DSH  (OFF_CS + 512)             // 107520: 128 floats
#define SMEM_TOTAL (OFF_DSH + 512)          // 108032

// Packed + swizzled W GEMM-slice image (matches smem A layout exactly):
// entry (h, col)  [col = half2 index 0..127, global k = 2*col]
//   dst[h*128 + ((col>>2) ^ (h&7))*4 + (col&3)] = half2(W[h][2col], W[h][2col+1])
__device__ __align__(16) uint32_t g_Wp[Hq * 128];

// ---------------- helpers ----------------
__device__ __forceinline__ float tanh_fast(float x) {
    float y; asm("tanh.approx.f32 %0, %1;" : "=f"(y) : "f"(x)); return y;
}
__device__ __forceinline__ void mma16(float* c, const uint32_t* a, const uint32_t* b) {
    asm volatile(
        "mma.sync.aligned.m16n8k16.row.col.f32.f16.f16.f32 "
        "{%0,%1,%2,%3}, {%4,%5,%6,%7}, {%8,%9}, {%0,%1,%2,%3};"
        : "+f"(c[0]), "+f"(c[1]), "+f"(c[2]), "+f"(c[3])
        : "r"(a[0]), "r"(a[1]), "r"(a[2]), "r"(a[3]), "r"(b[0]), "r"(b[1]));
}
__device__ __forceinline__ uint32_t pack2(float lo, float hi) {
    uint32_t r;
    asm("cvt.rn.f16x2.f32 %0, %2, %1;" : "=r"(r) : "f"(lo), "f"(hi));
    return r;
}
__device__ __forceinline__ void cpa16(uint32_t dst_smem, const void* src) {
    asm volatile("cp.async.ca.shared.global [%0], [%1], 16;"
                 :: "r"(dst_smem), "l"(src) : "memory");
}

// ---------------------------------------------------------------------------
// Kernel 0: pack W[:, 0:256] -> g_Wp (fp16, swizzled smem-image layout)
// ---------------------------------------------------------------------------
__global__ void pack_kernel(const float* __restrict__ W) {
    const int i = blockIdx.x * 256 + threadIdx.x;    // 0..16383
    const int col = i & 127;                         // half2 column
    const int h   = i >> 7;
    const float2 wv = *(const float2*)&W[h * 384 + 2 * col];
    const int dst = h * 128 + (((col >> 2) ^ (h & 7)) << 2) + (col & 3);
    g_Wp[dst] = pack2(wv.x, wv.y);
}

// ---------------------------------------------------------------------------
// Kernel 1: warp-autonomous fp16 HMMA GEMM + fused bias + tanh/v-dot
// Each warp owns a 128m x 16n output slice: private B ring in smem,
// shared read-only A image. ZERO __syncthreads in the main loop.
// grid (16, 256), 256 threads (8 warps), dyn smem 108032 B, occ 2.
// ---------------------------------------------------------------------------
__global__ __launch_bounds__(256, 2) void score_kernel(
    const float* __restrict__ st, const float* __restrict__ dy,
    const float* __restrict__ dec, const float* __restrict__ v,
    const float* __restrict__ W, float* __restrict__ out) {
    extern __shared__ __align__(16) char smem[];
    float* vs  = (float*)(smem + OFF_VS);
    float* cs  = (float*)(smem + OFF_CS);
    float* dsh = (float*)(smem + OFF_DSH);

    const int b  = blockIdx.y;
    const int n0 = blockIdx.x * BN;
    const int t  = threadIdx.x;
    const int w  = t >> 5;
    const int lane = t & 31;
    const int gid = lane >> 2;     // 0..7
    const int tig = lane & 3;      // 0..3

    const uint32_t sbA = (uint32_t)__cvta_generic_to_shared(smem + OFF_A);

    // ---- one-time A image load: 4096 x 16B granules, 16 per thread ----
    {
        const char* gA = (const char*)g_Wp;
#pragma unroll
        for (int i = 0; i < 16; i++)
            cpa16(sbA + (t + 256 * i) * 16, gA + (t + 256 * i) * 16);
        asm volatile("cp.async.commit_group;" ::: "memory");
    }

    // ---- stage dec/v; bias cs[h] = W[h][256:384] . dec[b] ----
    if (t < Hq) { vs[t] = v[t]; dsh[t] = dec[b * Hq + t]; }
    __syncthreads();
#pragma unroll
    for (int r = 0; r < 16; r++) {
        const int h = w * 16 + r;
        float p = 0.f;
#pragma unroll
        for (int i = 0; i < 4; i++)
            p = fmaf(W[h * 384 + 256 + lane + 32 * i], dsh[lane + 32 * i], p);
#pragma unroll
        for (int off = 16; off; off >>= 1)
            p += __shfl_xor_sync(0xffffffffu, p, off);
        if (lane == 0) cs[h] = p;
    }

    // ---- B prefetch chunk 0 into registers (warp-private slice) ----
    const float* base_st = st + (size_t)b * Hq * Nq;
    const float* base_dy = dy + (size_t)b * Hq * Nq;
    const int k2a = lane >> 2;           // k2 slot base (0..7), +8 for slot 1
    const int nq  = lane & 3;            // 4-float segment within 16-col slice
    const int ncol = n0 + w * 16 + nq * 4;

    float4 r0[2], r1[2];
#pragma unroll
    for (int i = 0; i < 2; i++) {
        const float* src = base_st + (size_t)(2 * (k2a + 8 * i)) * Nq + ncol;
        r0[i] = *(const float4*)src;
        r1[i] = *(const float4*)(src + Nq);
    }

    float acc[8][2][4];
#pragma unroll
    for (int i = 0; i < 8; i++)
#pragma unroll
        for (int j = 0; j < 2; j++)
#pragma unroll
            for (int q = 0; q < 4; q++) acc[i][j][q] = 0.f;

    // wait for A image + cs (barrier also publishes cs)
    asm volatile("cp.async.wait_group 0;" ::: "memory");
    __syncthreads();

    const uint32_t* A32 = (const uint32_t*)(smem + OFF_A);
    uint32_t* Bw = (uint32_t*)(smem + OFF_B) + w * (2 * 16 * BPS);

    // ================= warp-autonomous main loop (no CTA barriers) ========
    for (int c = 0; c < 8; c++) {
        uint32_t* Bb = Bw + (c & 1) * (16 * BPS);

        // ---- pack + STS chunk c into private buffer ----
#pragma unroll
        for (int i = 0; i < 2; i++) {
            uint4 pk;
            pk.x = pack2(r0[i].x, r1[i].x);
            pk.y = pack2(r0[i].y, r1[i].y);
            pk.z = pack2(r0[i].z, r1[i].z);
            pk.w = pack2(r0[i].w, r1[i].w);
            *(uint4*)&Bb[(k2a + 8 * i) * BPS + nq * 4] = pk;
        }
        __syncwarp();

        // ---- prefetch chunk c+1 (drains under MMA below) ----
        if (c < 7) {
#pragma unroll
            for (int i = 0; i < 2; i++) {
                const int gk = (c + 1) * BK + 2 * (k2a + 8 * i);
                const float* src = (gk < Hq ? base_st + (size_t)gk * Nq
                                            : base_dy + (size_t)(gk - Hq) * Nq) + ncol;
                r0[i] = *(const float4*)src;
                r1[i] = *(const float4*)(src + Nq);
            }
        }

        // ---- MMA: 128m x 16n, fragments from swizzled A + private B ----
#pragma unroll
        for (int kf = 0; kf < 2; kf++) {
            const int g0 = c * 4 + 2 * kf;
            const int c0 = (((g0)     ^ gid) << 2) | tig;
            const int c1 = (((g0 + 1) ^ gid) << 2) | tig;
            uint32_t bb[2][2];
#pragma unroll
            for (int nf = 0; nf < 2; nf++) {
                bb[nf][0] = Bb[(8 * kf + tig) * BPS + nf * 8 + gid];
                bb[nf][1] = Bb[(8 * kf + tig + 4) * BPS + nf * 8 + gid];
            }
#pragma unroll
            for (int mf = 0; mf < 8; mf++) {
                const uint32_t* ap = A32 + (mf * 16 + gid) * 128;
                uint32_t a[4];
                a[0] = ap[c0];
                a[1] = ap[1024 + c0];    // +8 rows
                a[2] = ap[c1];
                a[3] = ap[1024 + c1];
                mma16(acc[mf][0], a, bb[0]);
                mma16(acc[mf][1], a, bb[1]);
            }
        }
        __syncwarp();
    }

    // ---- epilogue: tanh + v-dot over all m (in-warp), direct store ----
#pragma unroll
    for (int nf = 0; nf < 2; nf++) {
        float p0 = 0.f, p1 = 0.f;
#pragma unroll
        for (int mf = 0; mf < 8; mf++) {
            const int h0 = mf * 16 + gid;
            const int h1 = h0 + 8;
            const float v0 = vs[h0], c0 = cs[h0];
            const float v1 = vs[h1], c1 = cs[h1];
            p0 = fmaf(v0, tanh_fast(acc[mf][nf][0] + c0), p0);
            p1 = fmaf(v0, tanh_fast(acc[mf][nf][1] + c0), p1);
            p0 = fmaf(v1, tanh_fast(acc[mf][nf][2] + c1), p0);
            p1 = fmaf(v1, tanh_fast(acc[mf][nf][3] + c1), p1);
        }
#pragma unroll
        for (int off = 4; off < 32; off <<= 1) {
            p0 += __shfl_xor_sync(0xffffffffu, p0, off);
            p1 += __shfl_xor_sync(0xffffffffu, p1, off);
        }
        if (gid == 0) {
            float* dst = out + (size_t)b * Nq + n0 + w * 16 + nf * 8 + 2 * tig;
            dst[0] = p0;
            dst[1] = p1;
        }
    }
}

// ---------------------------------------------------------------------------
// Kernel 2: in-place row softmax over N=2048
// ---------------------------------------------------------------------------
__global__ __launch_bounds__(256) void softmax_kernel(float* __restrict__ out) {
    __shared__ float sm[8];
    const int b = blockIdx.x, t = threadIdx.x;
    const int w = t >> 5, lane = t & 31;
    float* row = out + (size_t)b * Nq;

    float vals[8];
    float m = -1e30f;
#pragma unroll
    for (int i = 0; i < 8; i++) { vals[i] = row[t + 256 * i]; m = fmaxf(m, vals[i]); }
#pragma unroll
    for (int off = 16; off; off >>= 1)
        m = fmaxf(m, __shfl_xor_sync(0xffffffffu, m, off));
    if (lane == 0) sm[w] = m;
    __syncthreads();
    float M = sm[lane & 7];
#pragma unroll
    for (int off = 4; off; off >>= 1)
        M = fmaxf(M, __shfl_xor_sync(0xffffffffu, M, off));

    float sum = 0.f;
#pragma unroll
    for (int i = 0; i < 8; i++) { vals[i] = __expf(vals[i] - M); sum += vals[i]; }
#pragma unroll
    for (int off = 16; off; off >>= 1)
        sum += __shfl_xor_sync(0xffffffffu, sum, off);
    __syncthreads();
    if (lane == 0) sm[w] = sum;
    __syncthreads();
    float S = sm[lane & 7];
#pragma unroll
    for (int off = 4; off; off >>= 1)
        S += __shfl_xor_sync(0xffffffffu, S, off);

    const float inv = 1.f / S;
#pragma unroll
    for (int i = 0; i < 8; i++) row[t + 256 * i] = vals[i] * inv;
}

// ---------------------------------------------------------------------------
extern "C" void kernel_launch(void* const* d_in, const int* in_sizes, int n_in,
                              void* d_out, int out_size) {
    const float* st  = (const float*)d_in[0];
    const float* dy  = (const float*)d_in[1];
    const float* dec = (const float*)d_in[2];
    const float* v   = (const float*)d_in[3];
    const float* W   = (const float*)d_in[4];
    float* out = (float*)d_out;

    cudaFuncSetAttribute(score_kernel,
                         cudaFuncAttributeMaxDynamicSharedMemorySize, SMEM_TOTAL);

    pack_kernel<<<64, 256>>>(W);
    score_kernel<<<dim3(Nq / BN, Bq), 256, SMEM_TOTAL>>>(st, dy, dec, v, W, out);
    softmax_kernel<<<Bq, 256>>>(out);
}

// round 12
// speedup vs baseline: 1.3561x; 1.3561x over previous
#include <cuda_runtime.h>
#include <cuda_fp16.h>
#include <stdint.h>

#define Bq 256
#define Hq 128
#define Nq 2048
#define BM 128
#define BN 128
#define BK 32
#define BS2 136          // Bs16[.][k2][n] stride in half2 (conflict-free)
#define GRIDY 18

// dynamic smem offsets (bytes)
#define OFF_A   0                       // 128 x 128 half2, swizzled: 65536
#define OFF_B   65536                   // 2 x 16 x 136 x 4 = 17408
#define OFF_VS  (OFF_B + 17408)         // 82944: 128 floats
#define OFF_CS  (OFF_VS + 512)          // 83456: 128 floats
#define OFF_RED (OFF_CS + 512)          // 83968: 4 x 128 floats
#define SMEM_TOTAL (OFF_RED + 2048)     // 86016

// Packed+swizzled W GEMM-slice image (matches smem A layout exactly):
// (h, col): dst = h*128 + ((col>>2)^(h&7))*4 + (col&3); value = half2(W[h][2col], W[h][2col+1])
__device__ __align__(16) uint32_t g_Wp[Hq * 128];
// Precomputed bias: g_bias[b*128+h] = W[h][256:384] . dec[b]
__device__ float g_bias[Bq * Hq];

// ---------------- helpers ----------------
__device__ __forceinline__ float tanh_fast(float x) {
    float y; asm("tanh.approx.f32 %0, %1;" : "=f"(y) : "f"(x)); return y;
}
__device__ __forceinline__ void mma16(float* c, const uint32_t* a, const uint32_t* b) {
    asm volatile(
        "mma.sync.aligned.m16n8k16.row.col.f32.f16.f16.f32 "
        "{%0,%1,%2,%3}, {%4,%5,%6,%7}, {%8,%9}, {%0,%1,%2,%3};"
        : "+f"(c[0]), "+f"(c[1]), "+f"(c[2]), "+f"(c[3])
        : "r"(a[0]), "r"(a[1]), "r"(a[2]), "r"(a[3]), "r"(b[0]), "r"(b[1]));
}
__device__ __forceinline__ uint32_t pack2(float lo, float hi) {
    uint32_t r;
    asm("cvt.rn.f16x2.f32 %0, %2, %1;" : "=r"(r) : "f"(lo), "f"(hi));
    return r;
}
__device__ __forceinline__ void cpa16(uint32_t dst_smem, const void* src) {
    asm volatile("cp.async.ca.shared.global [%0], [%1], 16;"
                 :: "r"(dst_smem), "l"(src) : "memory");
}

// ---------------------------------------------------------------------------
// Kernel 0: prep. Blocks 0..63: pack W[:,0:256] -> swizzled fp16 image.
//           Blocks 64..319: bias[b][h] = W[h][256:384] . dec[b].
// ---------------------------------------------------------------------------
__global__ void prep_kernel(const float* __restrict__ W,
                            const float* __restrict__ dec) {
    const int bid = blockIdx.x;
    const int t = threadIdx.x;
    if (bid < 64) {
        const int i = bid * 256 + t;            // 0..16383
        const int col = i & 127;
        const int h   = i >> 7;
        const float2 wv = *(const float2*)&W[h * 384 + 2 * col];
        const int dst = h * 128 + (((col >> 2) ^ (h & 7)) << 2) + (col & 3);
        g_Wp[dst] = pack2(wv.x, wv.y);
    } else {
        const int b = bid - 64;
        __shared__ float dsh[Hq];
        const int w = t >> 5, lane = t & 31;
        if (t < Hq) dsh[t] = dec[b * Hq + t];
        __syncthreads();
#pragma unroll
        for (int r = 0; r < 16; r++) {
            const int h = w * 16 + r;
            float p = 0.f;
#pragma unroll
            for (int i = 0; i < 4; i++)
                p = fmaf(W[h * 384 + 256 + lane + 32 * i], dsh[lane + 32 * i], p);
#pragma unroll
            for (int off = 16; off; off >>= 1)
                p += __shfl_xor_sync(0xffffffffu, p, off);
            if (lane == 0) g_bias[b * Hq + h] = p;
        }
    }
}

// ---------------------------------------------------------------------------
// Kernel 1: batch-persistent fp16 HMMA GEMM + tanh/v-dot -> raw scores
// A image resident in smem across ~14 batches; per-batch loop runs R8's
// B pipeline (reg prefetch + pack + STS, double-buffered, 1 sync/chunk).
// grid (16, 18), 256 threads, dyn smem 86016 B, occ 2.
// ---------------------------------------------------------------------------
__global__ __launch_bounds__(256, 2) void score_kernel(
    const float* __restrict__ st, const float* __restrict__ dy,
    const float* __restrict__ v, float* __restrict__ out) {
    extern __shared__ __align__(16) char smem[];
    float* vs  = (float*)(smem + OFF_VS);
    float* cs  = (float*)(smem + OFF_CS);
    float* red = (float*)(smem + OFF_RED);
    const uint32_t* A32 = (const uint32_t*)(smem + OFF_A);
    __half2* Bs16 = (__half2*)(smem + OFF_B);   // [2][16][BS2]

    const int n0 = blockIdx.x * BN;
    const int by = blockIdx.y;
    const int nb     = (by < 4) ? 15 : 14;
    const int bstart = (by < 4) ? by * 15 : 60 + (by - 4) * 14;

    const int t  = threadIdx.x;
    const int w  = t >> 5;
    const int lane = t & 31;
    const int wm = w & 3;
    const int wn = w >> 2;
    const int gid = lane >> 2;
    const int tig = lane & 3;

    // ---- one-time A image load (overlaps batch-0 prologue) ----
    {
        const uint32_t sbA = (uint32_t)__cvta_generic_to_shared(smem + OFF_A);
        const char* gA = (const char*)g_Wp;
#pragma unroll
        for (int i = 0; i < 16; i++)
            cpa16(sbA + (t + 256 * i) * 16, gA + (t + 256 * i) * 16);
        asm volatile("cp.async.commit_group;" ::: "memory");
    }
    if (t < Hq) vs[t] = v[t];

    // B loader indices (loop-invariant)
    const int bk0 = t >> 5, bc = t & 31;
    const int bk1 = (t + 256) >> 5;

    for (int bi = 0; bi < nb; bi++) {
        const int b = bstart + bi;
        const float* base_st = st + (size_t)b * Hq * Nq;
        const float* base_dy = dy + (size_t)b * Hq * Nq;

        if (t < Hq) cs[t] = g_bias[b * Hq + t];

        float4 pb[2][2];
        // ---- prologue: LDG B chunk 0 + pack + STS into buffer 0 ----
        {
            const float* s0 = base_st + (size_t)(2 * bk0) * Nq + n0 + bc * 4;
            const float* s1 = base_st + (size_t)(2 * bk1) * Nq + n0 + bc * 4;
            pb[0][0] = *(const float4*)s0;   pb[0][1] = *(const float4*)(s0 + Nq);
            pb[1][0] = *(const float4*)s1;   pb[1][1] = *(const float4*)(s1 + Nq);
            uint4 b0, b1;
            b0.x = pack2(pb[0][0].x, pb[0][1].x); b0.y = pack2(pb[0][0].y, pb[0][1].y);
            b0.z = pack2(pb[0][0].z, pb[0][1].z); b0.w = pack2(pb[0][0].w, pb[0][1].w);
            b1.x = pack2(pb[1][0].x, pb[1][1].x); b1.y = pack2(pb[1][0].y, pb[1][1].y);
            b1.z = pack2(pb[1][0].z, pb[1][1].z); b1.w = pack2(pb[1][0].w, pb[1][1].w);
            *(uint4*)&Bs16[(0 * 16 + bk0) * BS2 + bc * 4] = b0;
            *(uint4*)&Bs16[(0 * 16 + bk1) * BS2 + bc * 4] = b1;
        }
        if (bi == 0) asm volatile("cp.async.wait_group 0;" ::: "memory");
        __syncthreads();

        float acc[2][8][4];
#pragma unroll
        for (int i = 0; i < 2; i++)
#pragma unroll
            for (int j = 0; j < 8; j++)
#pragma unroll
                for (int q = 0; q < 4; q++) acc[i][j][q] = 0.f;

        for (int c = 0; c < 8; c++) {
            const int cur = c & 1, nxt = cur ^ 1;

            // ---- LDG B chunk c+1 (drains under MMA) ----
            if (c < 7) {
                const int gk0 = (c + 1) * BK + 2 * bk0;
                const int gk1 = (c + 1) * BK + 2 * bk1;
                const float* s0 = (gk0 < Hq ? base_st + (size_t)gk0 * Nq
                                            : base_dy + (size_t)(gk0 - Hq) * Nq) + n0 + bc * 4;
                const float* s1 = (gk1 < Hq ? base_st + (size_t)gk1 * Nq
                                            : base_dy + (size_t)(gk1 - Hq) * Nq) + n0 + bc * 4;
                pb[0][0] = *(const float4*)s0;   pb[0][1] = *(const float4*)(s0 + Nq);
                pb[1][0] = *(const float4*)s1;   pb[1][1] = *(const float4*)(s1 + Nq);
            }

            // ---- MMA: A frags from resident swizzled image, B from Bs16 ----
            const __half2* Bb = Bs16 + cur * (16 * BS2);
#pragma unroll
            for (int kf = 0; kf < 2; kf++) {
                const int Q0 = c * 4 + kf * 2;
                const int x0 = ((Q0 ^ gid) << 2) + tig;
                const int x1 = (((Q0 + 1) ^ gid) << 2) + tig;
                uint32_t a[2][4], bb[8][2];
#pragma unroll
                for (int mf = 0; mf < 2; mf++) {
                    const int h0 = wm * 32 + mf * 16 + gid;   // h0&7 == gid
                    a[mf][0] = A32[h0 * 128 + x0];
                    a[mf][1] = A32[(h0 + 8) * 128 + x0];
                    a[mf][2] = A32[h0 * 128 + x1];
                    a[mf][3] = A32[(h0 + 8) * 128 + x1];
                }
                const int k2 = kf * 8;
#pragma unroll
                for (int nf = 0; nf < 8; nf++) {
                    const int n = wn * 64 + nf * 8;
                    bb[nf][0] = *(const uint32_t*)&Bb[(k2 + tig) * BS2 + n + gid];
                    bb[nf][1] = *(const uint32_t*)&Bb[(k2 + tig + 4) * BS2 + n + gid];
                }
#pragma unroll
                for (int mf = 0; mf < 2; mf++)
#pragma unroll
                    for (int nf = 0; nf < 8; nf++)
                        mma16(acc[mf][nf], a[mf], bb[nf]);
            }

            // ---- pack + STS B chunk c+1 into other buffer ----
            if (c < 7) {
                uint4 b0, b1;
                b0.x = pack2(pb[0][0].x, pb[0][1].x); b0.y = pack2(pb[0][0].y, pb[0][1].y);
                b0.z = pack2(pb[0][0].z, pb[0][1].z); b0.w = pack2(pb[0][0].w, pb[0][1].w);
                b1.x = pack2(pb[1][0].x, pb[1][1].x); b1.y = pack2(pb[1][0].y, pb[1][1].y);
                b1.z = pack2(pb[1][0].z, pb[1][1].z); b1.w = pack2(pb[1][0].w, pb[1][1].w);
                *(uint4*)&Bs16[(nxt * 16 + bk0) * BS2 + bc * 4] = b0;
                *(uint4*)&Bs16[(nxt * 16 + bk1) * BS2 + bc * 4] = b1;
            }
            __syncthreads();
        }

        // ---- epilogue: tanh + v-dot, reduce over m ----
#pragma unroll
        for (int nf = 0; nf < 8; nf++) {
            float p0 = 0.f, p1 = 0.f;
#pragma unroll
            for (int mf = 0; mf < 2; mf++) {
                const int r0 = wm * 32 + mf * 16 + gid;
                const int r1 = r0 + 8;
                const float v0 = vs[r0], c0 = cs[r0];
                const float v1 = vs[r1], c1 = cs[r1];
                p0 = fmaf(v0, tanh_fast(acc[mf][nf][0] + c0), p0);
                p1 = fmaf(v0, tanh_fast(acc[mf][nf][1] + c0), p1);
                p0 = fmaf(v1, tanh_fast(acc[mf][nf][2] + c1), p0);
                p1 = fmaf(v1, tanh_fast(acc[mf][nf][3] + c1), p1);
            }
#pragma unroll
            for (int off = 4; off < 32; off <<= 1) {
                p0 += __shfl_xor_sync(0xffffffffu, p0, off);
                p1 += __shfl_xor_sync(0xffffffffu, p1, off);
            }
            if (gid == 0) {
                const int col = wn * 64 + nf * 8 + 2 * tig;
                red[wm * BN + col]     = p0;
                red[wm * BN + col + 1] = p1;
            }
        }
        __syncthreads();

        if (t < BN)
            out[(size_t)b * Nq + n0 + t] =
                red[t] + red[BN + t] + red[2 * BN + t] + red[3 * BN + t];
    }
}

// ---------------------------------------------------------------------------
// Kernel 2: in-place row softmax over N=2048
// ---------------------------------------------------------------------------
__global__ __launch_bounds__(256) void softmax_kernel(float* __restrict__ out) {
    __shared__ float sm[8];
    const int b = blockIdx.x, t = threadIdx.x;
    const int w = t >> 5, lane = t & 31;
    float* row = out + (size_t)b * Nq;

    float vals[8];
    float m = -1e30f;
#pragma unroll
    for (int i = 0; i < 8; i++) { vals[i] = row[t + 256 * i]; m = fmaxf(m, vals[i]); }
#pragma unroll
    for (int off = 16; off; off >>= 1)
        m = fmaxf(m, __shfl_xor_sync(0xffffffffu, m, off));
    if (lane == 0) sm[w] = m;
    __syncthreads();
    float M = sm[lane & 7];
#pragma unroll
    for (int off = 4; off; off >>= 1)
        M = fmaxf(M, __shfl_xor_sync(0xffffffffu, M, off));

    float sum = 0.f;
#pragma unroll
    for (int i = 0; i < 8; i++) { vals[i] = __expf(vals[i] - M); sum += vals[i]; }
#pragma unroll
    for (int off = 16; off; off >>= 1)
        sum += __shfl_xor_sync(0xffffffffu, sum, off);
    __syncthreads();
    if (lane == 0) sm[w] = sum;
    __syncthreads();
    float S = sm[lane & 7];
#pragma unroll
    for (int off = 4; off; off >>= 1)
        S += __shfl_xor_sync(0xffffffffu, S, off);

    const float inv = 1.f / S;
#pragma unroll
    for (int i = 0; i < 8; i++) row[t + 256 * i] = vals[i] * inv;
}

// ---------------------------------------------------------------------------
extern "C" void kernel_launch(void* const* d_in, const int* in_sizes, int n_in,
                              void* d_out, int out_size) {
    const float* st  = (const float*)d_in[0];
    const float* dy  = (const float*)d_in[1];
    const float* dec = (const float*)d_in[2];
    const float* v   = (const float*)d_in[3];
    const float* W   = (const float*)d_in[4];
    float* out = (float*)d_out;

    cudaFuncSetAttribute(score_kernel,
                         cudaFuncAttributeMaxDynamicSharedMemorySize, SMEM_TOTAL);

    prep_kernel<<<64 + Bq, 256>>>(W, dec);
    score_kernel<<<dim3(Nq / BN, GRIDY), 256, SMEM_TOTAL>>>(st, dy, v, out);
    softmax_kernel<<<Bq, 256>>>(out);
}